// round 6
// baseline (speedup 1.0000x reference)
#include <cuda_runtime.h>
#include <cuda_bf16.h>
#include <cstdint>
#include <cstddef>

#define DIM     4096
#define HDIM    128
#define NHEADS  32
#define BSZ     2
#define SEQ     1024
#define CACHE   1024
#define TKV     2048
#define MROWS   2048   // BSZ*SEQ

// ---------------- scratch (static device memory; no allocations allowed) ----
// "split32" layout: per logical row of L fp32 elems, L/32 chunks of 128B:
// [32 x bf16 hi][32 x bf16 lo]; element e -> byte (e>>5)*128 + (e&31)*2 (hi), +64 (lo)
static __device__ __align__(16) char g_xs [(size_t)MROWS * DIM * 4];
static __device__ __align__(16) char g_wqs[(size_t)DIM * DIM * 4];
static __device__ __align__(16) char g_wks[(size_t)DIM * DIM * 4];
static __device__ __align__(16) char g_wvs[(size_t)DIM * DIM * 4];
static __device__ __align__(16) char g_wos[(size_t)DIM * DIM * 4];
static __device__ __align__(16) float g_q [(size_t)MROWS * DIM];   // fp32 pre-rope
static __device__ __align__(16) float g_k [(size_t)MROWS * DIM];
static __device__ __align__(16) float g_v [(size_t)MROWS * DIM];
static __device__ __align__(16) char g_qs [(size_t)MROWS * DIM * 4];             // roped q, split
static __device__ __align__(16) char g_krs[(size_t)BSZ * NHEADS * TKV * HDIM * 4]; // roped k, split
static __device__ __align__(16) char g_vts[(size_t)BSZ * NHEADS * HDIM * TKV * 4]; // v^T, split
static __device__ __align__(16) char g_cs [(size_t)MROWS * DIM * 4];             // ctx, split
static __device__ __align__(16) float g_sc[(size_t)BSZ * NHEADS * SEQ * TKV];    // scores fp32 -> probs split (in place)

// ---------------- helpers -----------------------------------------------------
__device__ __forceinline__ uint32_t smem_u32(const void* p) {
    uint32_t a;
    asm("{ .reg .u64 t; cvta.to.shared.u64 t, %1; cvt.u32.u64 %0, t; }"
        : "=r"(a) : "l"(p));
    return a;
}

__device__ __forceinline__ void cp16(uint32_t dst, const void* src) {
    asm volatile("cp.async.cg.shared.global [%0], [%1], 16;"
                 :: "r"(dst), "l"(src));
}
#define CP_COMMIT() asm volatile("cp.async.commit_group;" ::: "memory")
#define CP_WAIT1()  asm volatile("cp.async.wait_group 1;"  ::: "memory")

__device__ __forceinline__ void mma_bf16(float c[4], const uint32_t a[4],
                                         const uint32_t b[2]) {
    asm volatile(
        "mma.sync.aligned.m16n8k16.row.col.f32.bf16.bf16.f32 "
        "{%0,%1,%2,%3},{%4,%5,%6,%7},{%8,%9},{%0,%1,%2,%3};\n"
        : "+f"(c[0]), "+f"(c[1]), "+f"(c[2]), "+f"(c[3])
        : "r"(a[0]), "r"(a[1]), "r"(a[2]), "r"(a[3]),
          "r"(b[0]), "r"(b[1]));
}

// split pair of fp32 into packed bf16x2 hi and lo (low half = first element)
__device__ __forceinline__ void bsplit2(float x, float y,
                                        uint32_t& hi, uint32_t& lo) {
    __nv_bfloat16 hx = __float2bfloat16(x);
    __nv_bfloat16 hy = __float2bfloat16(y);
    __nv_bfloat16 lx = __float2bfloat16(x - __bfloat162float(hx));
    __nv_bfloat16 ly = __float2bfloat16(y - __bfloat162float(hy));
    uint16_t uhx = *(uint16_t*)&hx, uhy = *(uint16_t*)&hy;
    uint16_t ulx = *(uint16_t*)&lx, uly = *(uint16_t*)&ly;
    hi = (uint32_t)uhx | ((uint32_t)uhy << 16);
    lo = (uint32_t)ulx | ((uint32_t)uly << 16);
}

// ---------------- bf16 hi/lo 3-term GEMM ---------------------------------------
// C[M,N] = A[M,K] * B[N,K]^T, A/B in split32 layout (byte strides).
// Block 128x128, K-chunk 32, 3-stage cp.async, 256 thr (8 warps 2Mx4N),
// warp tile 64x32.  Per k16: acc += Ah*Bh + Ah*Bl + Al*Bh (fp32 accum).
// causal: skip block if n0 >= CACHE+m0+128.  kcap: clamp K to CACHE+m0+128.
// out_split: write C in split32 (else fp32).
__global__ __launch_bounds__(256, 2) void gemm_bf(
    const char* __restrict__ Ag, const char* __restrict__ Bg,
    char* __restrict__ Cg, int K, int ldaB, int ldbB, int ldcB,
    long long sAb, long long sAh, long long sBb, long long sBh,
    long long sCb, long long sCh, int nH,
    int causal, int kcap, int out_split)
{
    constexpr int ROWB = 144;            // smem row stride bytes (conflict-free)
    constexpr int BOFF = 128 * ROWB;     // B region offset
    constexpr int SWB  = 256 * ROWB;     // stage bytes (36864)
    extern __shared__ char smem[];

    const int z  = blockIdx.z;
    const int bb = z / nH, hh = z - bb * nH;
    const char* A = Ag + (size_t)bb * sAb + (size_t)hh * sAh;
    const char* B = Bg + (size_t)bb * sBb + (size_t)hh * sBh;
    char*       C = Cg + (size_t)bb * sCb + (size_t)hh * sCh;
    const int m0 = blockIdx.y << 7;
    const int n0 = blockIdx.x << 7;

    if (causal && n0 >= CACHE + m0 + 128) return;
    int Keff = K;
    if (kcap) { const int cap = CACHE + m0 + 128; if (cap < K) Keff = cap; }
    const int nt = Keff >> 5;

    const int tid  = threadIdx.x;
    const int lane = tid & 31, w = tid >> 5;
    const int wm = (w & 1) << 6;
    const int wn = (w >> 1) << 5;
    const int g  = lane >> 2, tq = lane & 3;

    const int crow = tid >> 3;            // 0..31
    const int off  = (tid & 7) << 4;      // 0..112 bytes
    const char* aP = A + (size_t)(m0 + crow) * ldaB + off;
    const char* bP = B + (size_t)(n0 + crow) * ldbB + off;
    const uint32_t sbu = smem_u32(smem);
    const uint32_t dA = sbu + (uint32_t)(crow * ROWB + off);
    const uint32_t dB = dA + BOFF;

    float acc[4][4][4];
#pragma unroll
    for (int i = 0; i < 4; i++)
#pragma unroll
        for (int j = 0; j < 4; j++)
#pragma unroll
            for (int l = 0; l < 4; l++) acc[i][j][l] = 0.f;

#define ISSUE(SOFF, T) do {                                                    \
    _Pragma("unroll")                                                          \
    for (int _i = 0; _i < 4; _i++)                                             \
        cp16(dA + (SOFF) + (uint32_t)(_i * 32 * ROWB),                         \
             aP + (size_t)(T) * 128 + (size_t)(_i * 32) * ldaB);               \
    _Pragma("unroll")                                                          \
    for (int _i = 0; _i < 4; _i++)                                             \
        cp16(dB + (SOFF) + (uint32_t)(_i * 32 * ROWB),                         \
             bP + (size_t)(T) * 128 + (size_t)(_i * 32) * ldbB);               \
} while (0)

#define COMPUTE(BUF) do {                                                      \
    const char* Ab = smem + (BUF) * SWB;                                       \
    const char* Bb = Ab + BOFF;                                                \
    _Pragma("unroll")                                                          \
    for (int s16 = 0; s16 < 2; s16++) {                                        \
        const int kb = s16 << 5;                                               \
        uint32_t bh[4][2], bl[4][2];                                           \
        _Pragma("unroll")                                                      \
        for (int nn = 0; nn < 4; nn++) {                                       \
            const char* bp = Bb + (wn + (nn << 3) + g) * ROWB + kb + (tq << 2);\
            bh[nn][0] = *(const uint32_t*)(bp);                                \
            bh[nn][1] = *(const uint32_t*)(bp + 16);                           \
            bl[nn][0] = *(const uint32_t*)(bp + 64);                           \
            bl[nn][1] = *(const uint32_t*)(bp + 80);                           \
        }                                                                      \
        _Pragma("unroll")                                                      \
        for (int mt = 0; mt < 4; mt++) {                                       \
            const char* ap = Ab + (wm + (mt << 4) + g) * ROWB + kb + (tq << 2);\
            uint32_t ah[4], al[4];                                             \
            ah[0] = *(const uint32_t*)(ap);                                    \
            ah[1] = *(const uint32_t*)(ap + 8 * ROWB);                         \
            ah[2] = *(const uint32_t*)(ap + 16);                               \
            ah[3] = *(const uint32_t*)(ap + 16 + 8 * ROWB);                    \
            al[0] = *(const uint32_t*)(ap + 64);                               \
            al[1] = *(const uint32_t*)(ap + 64 + 8 * ROWB);                    \
            al[2] = *(const uint32_t*)(ap + 80);                               \
            al[3] = *(const uint32_t*)(ap + 80 + 8 * ROWB);                    \
            _Pragma("unroll")                                                  \
            for (int nn = 0; nn < 4; nn++) {                                   \
                mma_bf16(acc[mt][nn], ah, bh[nn]);                             \
                mma_bf16(acc[mt][nn], ah, bl[nn]);                             \
                mma_bf16(acc[mt][nn], al, bh[nn]);                             \
            }                                                                  \
        }                                                                      \
    }                                                                          \
} while (0)

    ISSUE(0u, 0);            CP_COMMIT();
    ISSUE((uint32_t)SWB, 1); CP_COMMIT();

    int buf = 0;
    for (int t = 0; t < nt; ++t) {
        CP_WAIT1();
        __syncthreads();
        if (t + 2 < nt) {
            int nb = buf + 2; if (nb >= 3) nb -= 3;
            ISSUE((uint32_t)(nb * SWB), t + 2);
        }
        CP_COMMIT();
        COMPUTE(buf);
        buf = (buf == 2) ? 0 : buf + 1;
    }

    // ---------------- epilogue -------------------------------------------------
#pragma unroll
    for (int mt = 0; mt < 4; mt++) {
#pragma unroll
        for (int nn = 0; nn < 4; nn++) {
            const int row = m0 + wm + (mt << 4) + g;
            const int col = n0 + wn + (nn << 3) + (tq << 1);
            if (!out_split) {
                float2 v0; v0.x = acc[mt][nn][0]; v0.y = acc[mt][nn][1];
                float2 v1; v1.x = acc[mt][nn][2]; v1.y = acc[mt][nn][3];
                *(float2*)((float*)(C + (size_t)row * ldcB) + col)       = v0;
                *(float2*)((float*)(C + (size_t)(row + 8) * ldcB) + col) = v1;
            } else {
                const uint32_t cb = ((uint32_t)(col >> 5) << 7) + ((col & 31) << 1);
                uint32_t hi, lo;
                bsplit2(acc[mt][nn][0], acc[mt][nn][1], hi, lo);
                char* p0 = C + (size_t)row * ldcB + cb;
                *(uint32_t*)p0        = hi;
                *(uint32_t*)(p0 + 64) = lo;
                bsplit2(acc[mt][nn][2], acc[mt][nn][3], hi, lo);
                char* p1 = C + (size_t)(row + 8) * ldcB + cb;
                *(uint32_t*)p1        = hi;
                *(uint32_t*)(p1 + 64) = lo;
            }
        }
    }
#undef ISSUE
#undef COMPUTE
}

// ---------------- fp32 -> split32 conversion -----------------------------------
__global__ void split_tf(const float4* __restrict__ src, char* __restrict__ dst)
{
    const size_t i = (size_t)blockIdx.x * 256 + threadIdx.x;
    const float4 v = src[i];
    const size_t e = i * 4;
    uint32_t h0, l0, h1, l1;
    bsplit2(v.x, v.y, h0, l0);
    bsplit2(v.z, v.w, h1, l1);
    char* p = dst + ((e >> 5) << 7) + ((e & 31) << 1);
    *(uint2*)p        = make_uint2(h0, h1);
    *(uint2*)(p + 64) = make_uint2(l0, l1);
}

// ---------------- RoPE: q -> qs split; k -> xk fp32 + krs split; v -> xv ------
__global__ void rope_scatter(const float* __restrict__ q, const float* __restrict__ k,
                             const float* __restrict__ v,
                             const float* __restrict__ rope,
                             float* __restrict__ xk, float* __restrict__ xv,
                             char* __restrict__ qs, char* __restrict__ krs)
{
    const size_t idx = (size_t)blockIdx.x * 256 + threadIdx.x; // < 4194304
    const int j = (int)(idx & 63);
    const int h = (int)((idx >> 6) & 31);
    const int s = (int)((idx >> 11) & 1023);
    const int b = (int)(idx >> 21);

    const size_t src = ((size_t)(b * SEQ + s)) * DIM + h * HDIM + 2 * j;
    const float c  = rope[(size_t)(s * 64 + j) * 2];
    const float sn = rope[(size_t)(s * 64 + j) * 2 + 1];

    const float q0 = q[src], q1 = q[src + 1];
    {
        uint32_t hi, lo;
        bsplit2(q0 * c - q1 * sn, q0 * sn + q1 * c, hi, lo);
        char* p = qs + ((src >> 5) << 7) + ((src & 31) << 1);
        *(uint32_t*)p        = hi;
        *(uint32_t*)(p + 64) = lo;
    }

    const float k0 = k[src], k1 = k[src + 1];
    const float kr0 = k0 * c - k1 * sn;
    const float kr1 = k0 * sn + k1 * c;
    const size_t dst = (((size_t)(b * NHEADS + h)) * TKV + CACHE + s) * HDIM + 2 * j;
    xk[dst]     = kr0;
    xk[dst + 1] = kr1;
    {
        uint32_t hi, lo;
        bsplit2(kr0, kr1, hi, lo);
        char* p = krs + ((dst >> 5) << 7) + ((dst & 31) << 1);
        *(uint32_t*)p        = hi;
        *(uint32_t*)(p + 64) = lo;
    }

    xv[dst]     = v[src];
    xv[dst + 1] = v[src + 1];
}

// ---------------- caches -> xk/xv fp32 + krs split ------------------------------
__global__ void cache_copy(const float* __restrict__ kc,
                           const float* __restrict__ vc,
                           float* __restrict__ xk, float* __restrict__ xv,
                           char* __restrict__ krs)
{
    const size_t i4  = (size_t)blockIdx.x * 256 + threadIdx.x; // < 2097152
    const size_t src = i4 * 4;
    const size_t bh  = src >> 17;              // / (CACHE*HDIM)
    const size_t dst = src + bh * (size_t)(CACHE * HDIM);
    const float4 kv = *(const float4*)(kc + src);
    *(float4*)(xk + dst) = kv;
    uint32_t h0, l0, h1, l1;
    bsplit2(kv.x, kv.y, h0, l0);
    bsplit2(kv.z, kv.w, h1, l1);
    char* p = krs + ((dst >> 5) << 7) + ((dst & 31) << 1);
    *(uint2*)p        = make_uint2(h0, h1);
    *(uint2*)(p + 64) = make_uint2(l0, l1);
    *(float4*)(xv + dst) = *(const float4*)(vc + src);
}

// ---------------- transpose xv -> vts[b,h,d,t] (split) --------------------------
__global__ void transpose_v(const float* __restrict__ xv, char* __restrict__ vts)
{
    __shared__ float tile[32][33];
    const int bh = blockIdx.z;
    const int t0 = blockIdx.x << 5, d0 = blockIdx.y << 5;
    const float* src = xv + (size_t)bh * TKV * HDIM;
    const int tx = threadIdx.x, ty = threadIdx.y;  // 32 x 8
#pragma unroll
    for (int i = 0; i < 32; i += 8)
        tile[ty + i][tx] = src[(size_t)(t0 + ty + i) * HDIM + d0 + tx];
    __syncthreads();
    // each thread writes one pair of t-columns: pairs within a 32-chunk
    const int tp = (tx & 15) << 1;       // 0,2,..,30
    const int rr = ((tx >> 4) << 3) + ty; // 0..15
#pragma unroll
    for (int i = 0; i < 32; i += 16) {
        const int d = rr + i;
        const size_t ev = ((size_t)bh * HDIM + d0 + d) * TKV + t0 + tp;
        uint32_t hi, lo;
        bsplit2(tile[tp][d], tile[tp + 1][d], hi, lo);
        char* p = vts + ((ev >> 5) << 7) + ((ev & 31) << 1);
        *(uint32_t*)p        = hi;
        *(uint32_t*)(p + 64) = lo;
    }
}

// ---------------- causal softmax: fp32 scores -> split probs (in place) --------
__global__ void softmax_causal(float* __restrict__ S)
{
    const int s  = blockIdx.x;
    const int bh = blockIdx.y;
    float* row = S + ((size_t)bh * SEQ + s) * TKV;
    const int L    = CACHE + s + 1;
    const int capb = CACHE + (s & ~127) + 128;   // PV reads exactly [0, capb)
    const int tid = threadIdx.x;
    const float scale = 0.08838834764831845f; // 1/sqrt(128)

    float v[8];
    float m = -3.0e38f;
#pragma unroll
    for (int i = 0; i < 4; i++) {
        const int i0 = 2 * tid + (i << 9);
        v[2*i]   = (i0     < L) ? row[i0]     : -3.0e38f;
        v[2*i+1] = (i0 + 1 < L) ? row[i0 + 1] : -3.0e38f;
        m = fmaxf(m, fmaxf(v[2*i], v[2*i+1]));
    }
    __shared__ float red[8];
#pragma unroll
    for (int o = 16; o > 0; o >>= 1) m = fmaxf(m, __shfl_xor_sync(0xffffffffu, m, o));
    if ((tid & 31) == 0) red[tid >> 5] = m;
    __syncthreads();
    float bm = red[0];
#pragma unroll
    for (int i = 1; i < 8; i++) bm = fmaxf(bm, red[i]);

    float sum = 0.f;
#pragma unroll
    for (int i = 0; i < 8; i++) {
        if (v[i] > -1.0e38f) { v[i] = __expf(scale * (v[i] - bm)); sum += v[i]; }
        else                 { v[i] = 0.f; }
    }
#pragma unroll
    for (int o = 16; o > 0; o >>= 1) sum += __shfl_xor_sync(0xffffffffu, sum, o);
    __syncthreads();
    if ((tid & 31) == 0) red[tid >> 5] = sum;
    __syncthreads();
    float bs = 0.f;
#pragma unroll
    for (int i = 0; i < 8; i++) bs += red[i];
    const float inv = 1.f / bs;

    char* rowc = (char*)row;
#pragma unroll
    for (int i = 0; i < 4; i++) {
        const int i0 = 2 * tid + (i << 9);
        if (i0 < capb) {
            uint32_t hi, lo;
            bsplit2(v[2*i] * inv, v[2*i+1] * inv, hi, lo);
            char* p = rowc + ((i0 >> 5) << 7) + ((i0 & 31) << 1);
            *(uint32_t*)p        = hi;
            *(uint32_t*)(p + 64) = lo;
        }
    }
}

// ---------------- launch --------------------------------------------------------
extern "C" void kernel_launch(void* const* d_in, const int* in_sizes, int n_in,
                              void* d_out, int out_size)
{
    const float* x    = (const float*)d_in[0];
    const float* kc   = (const float*)d_in[1];
    const float* vc   = (const float*)d_in[2];
    const float* rope = (const float*)d_in[3];
    const float* Wq   = (const float*)d_in[4];
    const float* Wk   = (const float*)d_in[5];
    const float* Wv   = (const float*)d_in[6];
    const float* Wo   = (const float*)d_in[7];

    float* out = (float*)d_out;
    float* xk  = out + (size_t)BSZ * SEQ * DIM;               // +8388608
    float* xv  = xk + (size_t)BSZ * NHEADS * TKV * HDIM;      // +16777216

    char *xs, *wqs, *wks, *wvs, *wos, *qs, *krs, *vts, *cs;
    float *q, *k, *v, *sc;
    cudaGetSymbolAddress((void**)&xs,  g_xs);
    cudaGetSymbolAddress((void**)&wqs, g_wqs);
    cudaGetSymbolAddress((void**)&wks, g_wks);
    cudaGetSymbolAddress((void**)&wvs, g_wvs);
    cudaGetSymbolAddress((void**)&wos, g_wos);
    cudaGetSymbolAddress((void**)&q,   g_q);
    cudaGetSymbolAddress((void**)&k,   g_k);
    cudaGetSymbolAddress((void**)&v,   g_v);
    cudaGetSymbolAddress((void**)&qs,  g_qs);
    cudaGetSymbolAddress((void**)&krs, g_krs);
    cudaGetSymbolAddress((void**)&vts, g_vts);
    cudaGetSymbolAddress((void**)&cs,  g_cs);
    cudaGetSymbolAddress((void**)&sc,  g_sc);

    const int GSMEM = 3 * 256 * 144;   // 110592 bytes -> 2 CTA/SM
    static int smem_set = 0;
    if (!smem_set) {
        cudaFuncSetAttribute(gemm_bf, cudaFuncAttributeMaxDynamicSharedMemorySize, GSMEM);
        smem_set = 1;
    }

    const dim3 blk(256);

    // split inputs (x, Wq, Wk, Wv) -- Wo split deferred so a GEMM lands at ncu slot 6
    split_tf<<<MROWS * DIM / 1024, blk>>>((const float4*)x,  xs);
    split_tf<<<DIM * DIM / 1024,   blk>>>((const float4*)Wq, wqs);
    split_tf<<<DIM * DIM / 1024,   blk>>>((const float4*)Wk, wks);
    split_tf<<<DIM * DIM / 1024,   blk>>>((const float4*)Wv, wvs);

    // Q/K/V projections (fp32 outputs)
    const dim3 gp(DIM / 128, MROWS / 128, 1);
    gemm_bf<<<gp, blk, GSMEM>>>(xs, wqs, (char*)q, DIM, DIM*4, DIM*4, DIM*4,
                                0, 0, 0, 0, 0, 0, 1, 0, 0, 0);
    gemm_bf<<<gp, blk, GSMEM>>>(xs, wks, (char*)k, DIM, DIM*4, DIM*4, DIM*4,
                                0, 0, 0, 0, 0, 0, 1, 0, 0, 0);
    gemm_bf<<<gp, blk, GSMEM>>>(xs, wvs, (char*)v, DIM, DIM*4, DIM*4, DIM*4,
                                0, 0, 0, 0, 0, 0, 1, 0, 0, 0);

    split_tf<<<DIM * DIM / 1024,   blk>>>((const float4*)Wo, wos);

    cache_copy<<<8192, blk>>>(kc, vc, xk, xv, krs);
    rope_scatter<<<16384, blk>>>(q, k, v, rope, xk, xv, qs, krs);
    transpose_v<<<dim3(TKV / 32, HDIM / 32, BSZ * NHEADS), dim3(32, 8)>>>(xv, vts);

    // scores[b,h,s,t] = q . kr   (K=128, causal block skip, fp32 out)
    const dim3 gs(TKV / 128, SEQ / 128, BSZ * NHEADS);
    gemm_bf<<<gs, blk, GSMEM>>>(
        qs, krs, (char*)sc, HDIM, DIM*4, HDIM*4, TKV*4,
        (long long)SEQ * DIM * 4, (long long)HDIM * 4,
        (long long)NHEADS * TKV * HDIM * 4, (long long)TKV * HDIM * 4,
        (long long)NHEADS * SEQ * TKV * 4, (long long)SEQ * TKV * 4, NHEADS,
        1, 0, 0);

    const dim3 gsm(SEQ, BSZ * NHEADS);
    softmax_causal<<<gsm, blk>>>(sc);

    // ctx = P @ vt^T   (K capped by causal bound, split output)
    const dim3 gpv(HDIM / 128, SEQ / 128, BSZ * NHEADS);
    gemm_bf<<<gpv, blk, GSMEM>>>(
        (const char*)sc, vts, cs, TKV, TKV*4, TKV*4, DIM*4,
        (long long)NHEADS * SEQ * TKV * 4, (long long)SEQ * TKV * 4,
        (long long)NHEADS * HDIM * TKV * 4, (long long)HDIM * TKV * 4,
        (long long)SEQ * DIM * 4, (long long)HDIM * 4, NHEADS,
        0, 1, 1);

    // output = ctx @ Wo^T  (fp32 out)
    gemm_bf<<<gp, blk, GSMEM>>>(cs, wos, (char*)out, DIM, DIM*4, DIM*4, DIM*4,
                                0, 0, 0, 0, 0, 0, 1, 0, 0, 0);
}

// round 7
// speedup vs baseline: 2.1831x; 2.1831x over previous
#include <cuda_runtime.h>
#include <cuda_fp16.h>
#include <cstdint>
#include <cstddef>

#define DIM     4096
#define HDIM    128
#define NHEADS  32
#define BSZ     2
#define SEQ     1024
#define CACHE   1024
#define TKV     2048
#define MROWS   2048   // BSZ*SEQ

// ---------------- scratch (static device memory; no allocations allowed) ----
static __device__ __align__(16) __half g_xs [(size_t)MROWS * DIM];
static __device__ __align__(16) __half g_wqs[(size_t)DIM * DIM];
static __device__ __align__(16) __half g_wks[(size_t)DIM * DIM];
static __device__ __align__(16) __half g_wvs[(size_t)DIM * DIM];
static __device__ __align__(16) __half g_wos[(size_t)DIM * DIM];
static __device__ __align__(16) float  g_q  [(size_t)MROWS * DIM];   // fp32 pre-rope
static __device__ __align__(16) float  g_k  [(size_t)MROWS * DIM];
static __device__ __align__(16) float  g_v  [(size_t)MROWS * DIM];
static __device__ __align__(16) __half g_qs [(size_t)MROWS * DIM];               // roped q
static __device__ __align__(16) __half g_krs[(size_t)BSZ * NHEADS * TKV * HDIM]; // roped k + cache
static __device__ __align__(16) __half g_vts[(size_t)BSZ * NHEADS * HDIM * TKV]; // v^T
static __device__ __align__(16) __half g_cs [(size_t)MROWS * DIM];               // ctx
static __device__ __align__(16) float  g_sc [(size_t)BSZ * NHEADS * SEQ * TKV];  // scores fp32
static __device__ __align__(16) __half g_ps [(size_t)BSZ * NHEADS * SEQ * TKV];  // probs fp16

// ---------------- helpers -----------------------------------------------------
__device__ __forceinline__ uint32_t smem_u32(const void* p) {
    uint32_t a;
    asm("{ .reg .u64 t; cvta.to.shared.u64 t, %1; cvt.u32.u64 %0, t; }"
        : "=r"(a) : "l"(p));
    return a;
}

__device__ __forceinline__ void cp16(uint32_t dst, const void* src) {
    asm volatile("cp.async.cg.shared.global [%0], [%1], 16;"
                 :: "r"(dst), "l"(src));
}
#define CP_COMMIT() asm volatile("cp.async.commit_group;" ::: "memory")
#define CP_WAIT1()  asm volatile("cp.async.wait_group 1;"  ::: "memory")

__device__ __forceinline__ void mma_fp16(float c[4], const uint32_t a[4],
                                         const uint32_t b[2]) {
    asm volatile(
        "mma.sync.aligned.m16n8k16.row.col.f32.f16.f16.f32 "
        "{%0,%1,%2,%3},{%4,%5,%6,%7},{%8,%9},{%0,%1,%2,%3};\n"
        : "+f"(c[0]), "+f"(c[1]), "+f"(c[2]), "+f"(c[3])
        : "r"(a[0]), "r"(a[1]), "r"(a[2]), "r"(a[3]),
          "r"(b[0]), "r"(b[1]));
}

__device__ __forceinline__ uint32_t pack_h2(float x, float y) {
    __half2 h = __floats2half2_rn(x, y);     // x -> low half (element order)
    return *(uint32_t*)&h;
}

// ---------------- fp16 pipelined NT GEMM ---------------------------------------
// C[M,N] = A[M,K] * B[N,K]^T, A/B fp16 row-major (byte strides).
// Block 128x128, K-chunk 64, 3-stage cp.async, 256 thr (8 warps 2Mx4N),
// warp tile 64x32, fp32 accumulate.
// causal: skip block if n0 >= CACHE+m0+128.  kcap: clamp K to CACHE+m0+128.
// out_half: write C as fp16 (else fp32).
__global__ __launch_bounds__(256, 2) void gemm_fp16(
    const char* __restrict__ Ag, const char* __restrict__ Bg,
    char* __restrict__ Cg, int K, int ldaB, int ldbB, int ldcB,
    long long sAb, long long sAh, long long sBb, long long sBh,
    long long sCb, long long sCh, int nH,
    int causal, int kcap, int out_half)
{
    constexpr int ROWB = 144;            // smem row stride bytes (conflict-free)
    constexpr int BOFF = 128 * ROWB;     // B region offset
    constexpr int SWB  = 256 * ROWB;     // stage bytes (36864)
    extern __shared__ char smem[];

    const int z  = blockIdx.z;
    const int bb = z / nH, hh = z - bb * nH;
    const char* A = Ag + (size_t)bb * sAb + (size_t)hh * sAh;
    const char* B = Bg + (size_t)bb * sBb + (size_t)hh * sBh;
    char*       C = Cg + (size_t)bb * sCb + (size_t)hh * sCh;
    const int m0 = blockIdx.y << 7;
    const int n0 = blockIdx.x << 7;

    if (causal && n0 >= CACHE + m0 + 128) return;
    int Keff = K;
    if (kcap) { const int cap = CACHE + m0 + 128; if (cap < K) Keff = cap; }
    const int nt = Keff >> 6;            // K-chunk 64

    const int tid  = threadIdx.x;
    const int lane = tid & 31, w = tid >> 5;
    const int wm = (w & 1) << 6;
    const int wn = (w >> 1) << 5;
    const int g  = lane >> 2, tq = lane & 3;

    const int crow = tid >> 3;            // 0..31
    const int off  = (tid & 7) << 4;      // 0..112 bytes within 128B row
    const char* aP = A + (size_t)(m0 + crow) * ldaB + off;
    const char* bP = B + (size_t)(n0 + crow) * ldbB + off;
    const uint32_t sbu = smem_u32(smem);
    const uint32_t dA = sbu + (uint32_t)(crow * ROWB + off);
    const uint32_t dB = dA + BOFF;

    float acc[4][4][4];
#pragma unroll
    for (int i = 0; i < 4; i++)
#pragma unroll
        for (int j = 0; j < 4; j++)
#pragma unroll
            for (int l = 0; l < 4; l++) acc[i][j][l] = 0.f;

#define ISSUE(SOFF, T) do {                                                    \
    _Pragma("unroll")                                                          \
    for (int _i = 0; _i < 4; _i++)                                             \
        cp16(dA + (SOFF) + (uint32_t)(_i * 32 * ROWB),                         \
             aP + (size_t)(T) * 128 + (size_t)(_i * 32) * ldaB);               \
    _Pragma("unroll")                                                          \
    for (int _i = 0; _i < 4; _i++)                                             \
        cp16(dB + (SOFF) + (uint32_t)(_i * 32 * ROWB),                         \
             bP + (size_t)(T) * 128 + (size_t)(_i * 32) * ldbB);               \
} while (0)

#define COMPUTE(BUF) do {                                                      \
    const char* Ab = smem + (BUF) * SWB;                                       \
    const char* Bb = Ab + BOFF;                                                \
    _Pragma("unroll")                                                          \
    for (int s16 = 0; s16 < 4; s16++) {                                        \
        const int kb = s16 << 5;                                               \
        uint32_t bf[4][2];                                                     \
        _Pragma("unroll")                                                      \
        for (int nn = 0; nn < 4; nn++) {                                       \
            const char* bp = Bb + (wn + (nn << 3) + g) * ROWB + kb + (tq << 2);\
            bf[nn][0] = *(const uint32_t*)(bp);                                \
            bf[nn][1] = *(const uint32_t*)(bp + 16);                           \
        }                                                                      \
        _Pragma("unroll")                                                      \
        for (int mt = 0; mt < 4; mt++) {                                       \
            const char* ap = Ab + (wm + (mt << 4) + g) * ROWB + kb + (tq << 2);\
            uint32_t af[4];                                                    \
            af[0] = *(const uint32_t*)(ap);                                    \
            af[1] = *(const uint32_t*)(ap + 8 * ROWB);                         \
            af[2] = *(const uint32_t*)(ap + 16);                               \
            af[3] = *(const uint32_t*)(ap + 16 + 8 * ROWB);                    \
            _Pragma("unroll")                                                  \
            for (int nn = 0; nn < 4; nn++)                                     \
                mma_fp16(acc[mt][nn], af, bf[nn]);                             \
        }                                                                      \
    }                                                                          \
} while (0)

    ISSUE(0u, 0);            CP_COMMIT();
    if (nt > 1) { ISSUE((uint32_t)SWB, 1); }
    CP_COMMIT();

    int buf = 0;
    for (int t = 0; t < nt; ++t) {
        CP_WAIT1();
        __syncthreads();
        if (t + 2 < nt) {
            int nb = buf + 2; if (nb >= 3) nb -= 3;
            ISSUE((uint32_t)(nb * SWB), t + 2);
        }
        CP_COMMIT();
        COMPUTE(buf);
        buf = (buf == 2) ? 0 : buf + 1;
    }

    // ---------------- epilogue -------------------------------------------------
#pragma unroll
    for (int mt = 0; mt < 4; mt++) {
#pragma unroll
        for (int nn = 0; nn < 4; nn++) {
            const int row = m0 + wm + (mt << 4) + g;
            const int col = n0 + wn + (nn << 3) + (tq << 1);
            if (!out_half) {
                float2 v0; v0.x = acc[mt][nn][0]; v0.y = acc[mt][nn][1];
                float2 v1; v1.x = acc[mt][nn][2]; v1.y = acc[mt][nn][3];
                *(float2*)((float*)(C + (size_t)row * ldcB) + col)       = v0;
                *(float2*)((float*)(C + (size_t)(row + 8) * ldcB) + col) = v1;
            } else {
                *(uint32_t*)(C + (size_t)row * ldcB + col * 2) =
                    pack_h2(acc[mt][nn][0], acc[mt][nn][1]);
                *(uint32_t*)(C + (size_t)(row + 8) * ldcB + col * 2) =
                    pack_h2(acc[mt][nn][2], acc[mt][nn][3]);
            }
        }
    }
#undef ISSUE
#undef COMPUTE
}

// ---------------- fp32 -> fp16 conversion --------------------------------------
__global__ void to_half(const float4* __restrict__ src, __half* __restrict__ dst)
{
    const size_t i = (size_t)blockIdx.x * 256 + threadIdx.x;
    const float4 v = src[i];
    uint2 o;
    o.x = pack_h2(v.x, v.y);
    o.y = pack_h2(v.z, v.w);
    *(uint2*)(dst + i * 4) = o;
}

// ---------------- RoPE: q -> qs fp16; k -> xk fp32 + krs fp16; v -> xv --------
__global__ void rope_scatter(const float* __restrict__ q, const float* __restrict__ k,
                             const float* __restrict__ v,
                             const float* __restrict__ rope,
                             float* __restrict__ xk, float* __restrict__ xv,
                             __half* __restrict__ qs, __half* __restrict__ krs)
{
    const size_t idx = (size_t)blockIdx.x * 256 + threadIdx.x; // < 4194304
    const int j = (int)(idx & 63);
    const int h = (int)((idx >> 6) & 31);
    const int s = (int)((idx >> 11) & 1023);
    const int b = (int)(idx >> 21);

    const size_t src = ((size_t)(b * SEQ + s)) * DIM + h * HDIM + 2 * j;
    const float c  = rope[(size_t)(s * 64 + j) * 2];
    const float sn = rope[(size_t)(s * 64 + j) * 2 + 1];

    const float q0 = q[src], q1 = q[src + 1];
    *(uint32_t*)(qs + src) = pack_h2(q0 * c - q1 * sn, q0 * sn + q1 * c);

    const float k0 = k[src], k1 = k[src + 1];
    const float kr0 = k0 * c - k1 * sn;
    const float kr1 = k0 * sn + k1 * c;
    const size_t dst = (((size_t)(b * NHEADS + h)) * TKV + CACHE + s) * HDIM + 2 * j;
    xk[dst]     = kr0;
    xk[dst + 1] = kr1;
    *(uint32_t*)(krs + dst) = pack_h2(kr0, kr1);

    xv[dst]     = v[src];
    xv[dst + 1] = v[src + 1];
}

// ---------------- caches -> xk/xv fp32 + krs fp16 -------------------------------
__global__ void cache_copy(const float* __restrict__ kc,
                           const float* __restrict__ vc,
                           float* __restrict__ xk, float* __restrict__ xv,
                           __half* __restrict__ krs)
{
    const size_t i4  = (size_t)blockIdx.x * 256 + threadIdx.x; // < 2097152
    const size_t src = i4 * 4;
    const size_t bh  = src >> 17;              // / (CACHE*HDIM)
    const size_t dst = src + bh * (size_t)(CACHE * HDIM);
    const float4 kv = *(const float4*)(kc + src);
    *(float4*)(xk + dst) = kv;
    uint2 o;
    o.x = pack_h2(kv.x, kv.y);
    o.y = pack_h2(kv.z, kv.w);
    *(uint2*)(krs + dst) = o;
    *(float4*)(xv + dst) = *(const float4*)(vc + src);
}

// ---------------- transpose xv -> vts[b,h,d,t] fp16 -----------------------------
__global__ void transpose_v(const float* __restrict__ xv, __half* __restrict__ vts)
{
    __shared__ float tile[32][33];
    const int bh = blockIdx.z;
    const int t0 = blockIdx.x << 5, d0 = blockIdx.y << 5;
    const float* src = xv + (size_t)bh * TKV * HDIM;
    const int tx = threadIdx.x, ty = threadIdx.y;  // 32 x 8
#pragma unroll
    for (int i = 0; i < 32; i += 8)
        tile[ty + i][tx] = src[(size_t)(t0 + ty + i) * HDIM + d0 + tx];
    __syncthreads();
    const int tp = (tx & 15) << 1;        // t-pair: 0,2,..,30
    const int rr = ((tx >> 4) << 3) + ty; // 0..15
#pragma unroll
    for (int i = 0; i < 32; i += 16) {
        const int d = rr + i;
        const size_t ev = ((size_t)bh * HDIM + d0 + d) * TKV + t0 + tp;
        *(uint32_t*)(vts + ev) = pack_h2(tile[tp][d], tile[tp + 1][d]);
    }
}

// ---------------- causal softmax: fp32 scores -> fp16 probs ---------------------
__global__ void softmax_causal(const float* __restrict__ S, __half* __restrict__ P)
{
    const int s  = blockIdx.x;
    const int bh = blockIdx.y;
    const float* row = S + ((size_t)bh * SEQ + s) * TKV;
    __half*      po  = P + ((size_t)bh * SEQ + s) * TKV;
    const int L    = CACHE + s + 1;
    const int capb = CACHE + (s & ~127) + 128;   // PV reads exactly [0, capb)
    const int tid = threadIdx.x;
    const float scale = 0.08838834764831845f; // 1/sqrt(128)

    float v[8];
    float m = -3.0e38f;
#pragma unroll
    for (int i = 0; i < 4; i++) {
        const int i0 = 2 * tid + (i << 9);
        v[2*i]   = (i0     < L) ? row[i0]     : -3.0e38f;
        v[2*i+1] = (i0 + 1 < L) ? row[i0 + 1] : -3.0e38f;
        m = fmaxf(m, fmaxf(v[2*i], v[2*i+1]));
    }
    __shared__ float red[8];
#pragma unroll
    for (int o = 16; o > 0; o >>= 1) m = fmaxf(m, __shfl_xor_sync(0xffffffffu, m, o));
    if ((tid & 31) == 0) red[tid >> 5] = m;
    __syncthreads();
    float bm = red[0];
#pragma unroll
    for (int i = 1; i < 8; i++) bm = fmaxf(bm, red[i]);

    float sum = 0.f;
#pragma unroll
    for (int i = 0; i < 8; i++) {
        if (v[i] > -1.0e38f) { v[i] = __expf(scale * (v[i] - bm)); sum += v[i]; }
        else                 { v[i] = 0.f; }
    }
#pragma unroll
    for (int o = 16; o > 0; o >>= 1) sum += __shfl_xor_sync(0xffffffffu, sum, o);
    __syncthreads();
    if ((tid & 31) == 0) red[tid >> 5] = sum;
    __syncthreads();
    float bs = 0.f;
#pragma unroll
    for (int i = 0; i < 8; i++) bs += red[i];
    const float inv = 1.f / bs;

#pragma unroll
    for (int i = 0; i < 4; i++) {
        const int i0 = 2 * tid + (i << 9);
        if (i0 < capb)
            *(uint32_t*)(po + i0) = pack_h2(v[2*i] * inv, v[2*i+1] * inv);
    }
}

// ---------------- launch --------------------------------------------------------
extern "C" void kernel_launch(void* const* d_in, const int* in_sizes, int n_in,
                              void* d_out, int out_size)
{
    const float* x    = (const float*)d_in[0];
    const float* kc   = (const float*)d_in[1];
    const float* vc   = (const float*)d_in[2];
    const float* rope = (const float*)d_in[3];
    const float* Wq   = (const float*)d_in[4];
    const float* Wk   = (const float*)d_in[5];
    const float* Wv   = (const float*)d_in[6];
    const float* Wo   = (const float*)d_in[7];

    float* out = (float*)d_out;
    float* xk  = out + (size_t)BSZ * SEQ * DIM;               // +8388608
    float* xv  = xk + (size_t)BSZ * NHEADS * TKV * HDIM;      // +16777216

    __half *xs, *wqs, *wks, *wvs, *wos, *qs, *krs, *vts, *cs, *ps;
    float *q, *k, *v, *sc;
    cudaGetSymbolAddress((void**)&xs,  g_xs);
    cudaGetSymbolAddress((void**)&wqs, g_wqs);
    cudaGetSymbolAddress((void**)&wks, g_wks);
    cudaGetSymbolAddress((void**)&wvs, g_wvs);
    cudaGetSymbolAddress((void**)&wos, g_wos);
    cudaGetSymbolAddress((void**)&q,   g_q);
    cudaGetSymbolAddress((void**)&k,   g_k);
    cudaGetSymbolAddress((void**)&v,   g_v);
    cudaGetSymbolAddress((void**)&qs,  g_qs);
    cudaGetSymbolAddress((void**)&krs, g_krs);
    cudaGetSymbolAddress((void**)&vts, g_vts);
    cudaGetSymbolAddress((void**)&cs,  g_cs);
    cudaGetSymbolAddress((void**)&sc,  g_sc);
    cudaGetSymbolAddress((void**)&ps,  g_ps);

    const int GSMEM = 3 * 256 * 144;   // 110592 bytes -> 2 CTA/SM
    static int smem_set = 0;
    if (!smem_set) {
        cudaFuncSetAttribute(gemm_fp16, cudaFuncAttributeMaxDynamicSharedMemorySize, GSMEM);
        smem_set = 1;
    }

    const dim3 blk(256);

    // convert inputs to fp16
    to_half<<<MROWS * DIM / 1024, blk>>>((const float4*)x,  xs);
    to_half<<<DIM * DIM / 1024,   blk>>>((const float4*)Wq, wqs);
    to_half<<<DIM * DIM / 1024,   blk>>>((const float4*)Wk, wks);
    to_half<<<DIM * DIM / 1024,   blk>>>((const float4*)Wv, wvs);

    // Q/K/V projections (fp32 outputs)
    const dim3 gp(DIM / 128, MROWS / 128, 1);
    gemm_fp16<<<gp, blk, GSMEM>>>((const char*)xs, (const char*)wqs, (char*)q,
                                  DIM, DIM*2, DIM*2, DIM*4,
                                  0, 0, 0, 0, 0, 0, 1, 0, 0, 0);
    gemm_fp16<<<gp, blk, GSMEM>>>((const char*)xs, (const char*)wks, (char*)k,
                                  DIM, DIM*2, DIM*2, DIM*4,
                                  0, 0, 0, 0, 0, 0, 1, 0, 0, 0);
    gemm_fp16<<<gp, blk, GSMEM>>>((const char*)xs, (const char*)wvs, (char*)v,
                                  DIM, DIM*2, DIM*2, DIM*4,
                                  0, 0, 0, 0, 0, 0, 1, 0, 0, 0);

    to_half<<<DIM * DIM / 1024,   blk>>>((const float4*)Wo, wos);

    cache_copy<<<8192, blk>>>(kc, vc, xk, xv, krs);
    rope_scatter<<<16384, blk>>>(q, k, v, rope, xk, xv, qs, krs);
    transpose_v<<<dim3(TKV / 32, HDIM / 32, BSZ * NHEADS), dim3(32, 8)>>>(xv, vts);

    // scores[b,h,s,t] = q . kr   (K=128, causal block skip, fp32 out)
    const dim3 gs(TKV / 128, SEQ / 128, BSZ * NHEADS);
    gemm_fp16<<<gs, blk, GSMEM>>>(
        (const char*)qs, (const char*)krs, (char*)sc, HDIM,
        DIM*2, HDIM*2, TKV*4,
        (long long)SEQ * DIM * 2, (long long)HDIM * 2,
        (long long)NHEADS * TKV * HDIM * 2, (long long)TKV * HDIM * 2,
        (long long)NHEADS * SEQ * TKV * 4, (long long)SEQ * TKV * 4, NHEADS,
        1, 0, 0);

    const dim3 gsm(SEQ, BSZ * NHEADS);
    softmax_causal<<<gsm, blk>>>(sc, ps);

    // ctx = P @ vt^T   (K capped by causal bound, fp16 output)
    const dim3 gpv(HDIM / 128, SEQ / 128, BSZ * NHEADS);
    gemm_fp16<<<gpv, blk, GSMEM>>>(
        (const char*)ps, (const char*)vts, (char*)cs, TKV,
        TKV*2, TKV*2, DIM*2,
        (long long)NHEADS * SEQ * TKV * 2, (long long)SEQ * TKV * 2,
        (long long)NHEADS * HDIM * TKV * 2, (long long)HDIM * TKV * 2,
        (long long)SEQ * DIM * 2, (long long)HDIM * 2, NHEADS,
        0, 1, 1);

    // output = ctx @ Wo^T  (fp32 out)
    gemm_fp16<<<gp, blk, GSMEM>>>((const char*)cs, (const char*)wos, (char*)out,
                                  DIM, DIM*2, DIM*2, DIM*4,
                                  0, 0, 0, 0, 0, 0, 1, 0, 0, 0);
}

// round 8
// speedup vs baseline: 2.4085x; 1.1032x over previous
#include <cuda_runtime.h>
#include <cuda_fp16.h>
#include <cstdint>
#include <cstddef>

#define DIM     4096
#define HDIM    128
#define NHEADS  32
#define BSZ     2
#define SEQ     1024
#define CACHE   1024
#define TKV     2048
#define MROWS   2048   // BSZ*SEQ

// ---------------- scratch (static device memory; no allocations allowed) ----
static __device__ __align__(16) __half g_xs [(size_t)MROWS * DIM];
static __device__ __align__(16) __half g_wqs[(size_t)DIM * DIM];
static __device__ __align__(16) __half g_wks[(size_t)DIM * DIM];
static __device__ __align__(16) __half g_wvs[(size_t)DIM * DIM];
static __device__ __align__(16) __half g_wos[(size_t)DIM * DIM];
static __device__ __align__(16) float  g_q  [(size_t)MROWS * DIM];   // fp32 pre-rope
static __device__ __align__(16) float  g_k  [(size_t)MROWS * DIM];
static __device__ __align__(16) float  g_v  [(size_t)MROWS * DIM];
static __device__ __align__(16) __half g_qs [(size_t)MROWS * DIM];               // roped q
static __device__ __align__(16) __half g_krs[(size_t)BSZ * NHEADS * TKV * HDIM]; // roped k + cache
static __device__ __align__(16) __half g_vts[(size_t)BSZ * NHEADS * HDIM * TKV]; // v^T
static __device__ __align__(16) __half g_cs [(size_t)MROWS * DIM];               // ctx

// ---------------- helpers -----------------------------------------------------
__device__ __forceinline__ uint32_t smem_u32(const void* p) {
    uint32_t a;
    asm("{ .reg .u64 t; cvta.to.shared.u64 t, %1; cvt.u32.u64 %0, t; }"
        : "=r"(a) : "l"(p));
    return a;
}

__device__ __forceinline__ void cp16(uint32_t dst, const void* src) {
    asm volatile("cp.async.cg.shared.global [%0], [%1], 16;"
                 :: "r"(dst), "l"(src));
}
#define CP_COMMIT() asm volatile("cp.async.commit_group;" ::: "memory")
#define CP_WAIT1()  asm volatile("cp.async.wait_group 1;"  ::: "memory")

__device__ __forceinline__ void mma_fp16(float c[4], const uint32_t a[4],
                                         const uint32_t b[2]) {
    asm volatile(
        "mma.sync.aligned.m16n8k16.row.col.f32.f16.f16.f32 "
        "{%0,%1,%2,%3},{%4,%5,%6,%7},{%8,%9},{%0,%1,%2,%3};\n"
        : "+f"(c[0]), "+f"(c[1]), "+f"(c[2]), "+f"(c[3])
        : "r"(a[0]), "r"(a[1]), "r"(a[2]), "r"(a[3]),
          "r"(b[0]), "r"(b[1]));
}

__device__ __forceinline__ uint32_t pack_h2(float x, float y) {
    __half2 h = __floats2half2_rn(x, y);     // x -> low half (element order)
    return *(uint32_t*)&h;
}

// ---------------- fp16 pipelined NT GEMM (projections + Wo) --------------------
// C[M,N] = A[M,K] * B[N,K]^T, fp16 in, fp32 accumulate.
// Block 128x128, K-chunk 64, 3-stage cp.async, 256 thr (8 warps 2Mx4N).
__global__ __launch_bounds__(256, 2) void gemm_fp16(
    const char* __restrict__ Ag, const char* __restrict__ Bg,
    char* __restrict__ Cg, int K, int ldaB, int ldbB, int ldcB,
    int out_half)
{
    constexpr int ROWB = 144;
    constexpr int BOFF = 128 * ROWB;
    constexpr int SWB  = 256 * ROWB;
    extern __shared__ char smem[];

    const char* A = Ag;
    const char* B = Bg;
    char*       C = Cg;
    const int m0 = blockIdx.y << 7;
    const int n0 = blockIdx.x << 7;
    const int nt = K >> 6;

    const int tid  = threadIdx.x;
    const int lane = tid & 31, w = tid >> 5;
    const int wm = (w & 1) << 6;
    const int wn = (w >> 1) << 5;
    const int g  = lane >> 2, tq = lane & 3;

    const int crow = tid >> 3;
    const int off  = (tid & 7) << 4;
    const char* aP = A + (size_t)(m0 + crow) * ldaB + off;
    const char* bP = B + (size_t)(n0 + crow) * ldbB + off;
    const uint32_t sbu = smem_u32(smem);
    const uint32_t dA = sbu + (uint32_t)(crow * ROWB + off);
    const uint32_t dB = dA + BOFF;

    float acc[4][4][4];
#pragma unroll
    for (int i = 0; i < 4; i++)
#pragma unroll
        for (int j = 0; j < 4; j++)
#pragma unroll
            for (int l = 0; l < 4; l++) acc[i][j][l] = 0.f;

#define ISSUE(SOFF, T) do {                                                    \
    _Pragma("unroll")                                                          \
    for (int _i = 0; _i < 4; _i++)                                             \
        cp16(dA + (SOFF) + (uint32_t)(_i * 32 * ROWB),                         \
             aP + (size_t)(T) * 128 + (size_t)(_i * 32) * ldaB);               \
    _Pragma("unroll")                                                          \
    for (int _i = 0; _i < 4; _i++)                                             \
        cp16(dB + (SOFF) + (uint32_t)(_i * 32 * ROWB),                         \
             bP + (size_t)(T) * 128 + (size_t)(_i * 32) * ldbB);               \
} while (0)

#define COMPUTE(BUF) do {                                                      \
    const char* Ab = smem + (BUF) * SWB;                                       \
    const char* Bb = Ab + BOFF;                                                \
    _Pragma("unroll")                                                          \
    for (int s16 = 0; s16 < 4; s16++) {                                        \
        const int kb = s16 << 5;                                               \
        uint32_t bf[4][2];                                                     \
        _Pragma("unroll")                                                      \
        for (int nn = 0; nn < 4; nn++) {                                       \
            const char* bp = Bb + (wn + (nn << 3) + g) * ROWB + kb + (tq << 2);\
            bf[nn][0] = *(const uint32_t*)(bp);                                \
            bf[nn][1] = *(const uint32_t*)(bp + 16);                           \
        }                                                                      \
        _Pragma("unroll")                                                      \
        for (int mt = 0; mt < 4; mt++) {                                       \
            const char* ap = Ab + (wm + (mt << 4) + g) * ROWB + kb + (tq << 2);\
            uint32_t af[4];                                                    \
            af[0] = *(const uint32_t*)(ap);                                    \
            af[1] = *(const uint32_t*)(ap + 8 * ROWB);                         \
            af[2] = *(const uint32_t*)(ap + 16);                               \
            af[3] = *(const uint32_t*)(ap + 16 + 8 * ROWB);                    \
            _Pragma("unroll")                                                  \
            for (int nn = 0; nn < 4; nn++)                                     \
                mma_fp16(acc[mt][nn], af, bf[nn]);                             \
        }                                                                      \
    }                                                                          \
} while (0)

    ISSUE(0u, 0);            CP_COMMIT();
    ISSUE((uint32_t)SWB, 1); CP_COMMIT();

    int buf = 0;
    for (int t = 0; t < nt; ++t) {
        CP_WAIT1();
        __syncthreads();
        if (t + 2 < nt) {
            int nb = buf + 2; if (nb >= 3) nb -= 3;
            ISSUE((uint32_t)(nb * SWB), t + 2);
        }
        CP_COMMIT();
        COMPUTE(buf);
        buf = (buf == 2) ? 0 : buf + 1;
    }

#pragma unroll
    for (int mt = 0; mt < 4; mt++) {
#pragma unroll
        for (int nn = 0; nn < 4; nn++) {
            const int row = m0 + wm + (mt << 4) + g;
            const int col = n0 + wn + (nn << 3) + (tq << 1);
            if (!out_half) {
                float2 v0; v0.x = acc[mt][nn][0]; v0.y = acc[mt][nn][1];
                float2 v1; v1.x = acc[mt][nn][2]; v1.y = acc[mt][nn][3];
                *(float2*)((float*)(C + (size_t)row * ldcB) + col)       = v0;
                *(float2*)((float*)(C + (size_t)(row + 8) * ldcB) + col) = v1;
            } else {
                *(uint32_t*)(C + (size_t)row * ldcB + col * 2) =
                    pack_h2(acc[mt][nn][0], acc[mt][nn][1]);
                *(uint32_t*)(C + (size_t)(row + 8) * ldcB + col * 2) =
                    pack_h2(acc[mt][nn][2], acc[mt][nn][3]);
            }
        }
    }
#undef ISSUE
#undef COMPUTE
}

// ---------------- fused flash attention -----------------------------------------
// One CTA = one (bh, 128-query block). 8 warps, each owns 16 q rows x all kv.
// Q resident in smem; K,V^T tiles (128 kv) double-buffered via cp.async.
// S in regs -> online softmax (exp2, folded scale) -> P reg-reuse as A frags
// -> PV accumulate into O regs -> normalize -> fp16 ctx.
__global__ __launch_bounds__(256) void flash_attn(
    const __half* __restrict__ qs, const __half* __restrict__ krs,
    const __half* __restrict__ vts, __half* __restrict__ cs)
{
    constexpr int RB  = 272;                // smem row stride bytes (conflict-free)
    constexpr int TSZ = 128 * RB;           // one 128-row tile (34816 B)
    extern __shared__ char smem[];
    char* Qs = smem;                        // Q tile
    char* Ks = smem + TSZ;                  // K tiles (2 buffers)
    char* Vs = smem + 3 * TSZ;              // V^T tiles (2 buffers)
    const uint32_t sbu = smem_u32(smem);

    const int qblk = 7 - blockIdx.x;        // heavy blocks scheduled first
    const int bh   = blockIdx.y;
    const int b    = bh >> 5;
    const int h    = bh & 31;
    const int m0   = qblk << 7;
    const int nt   = 9 + qblk;              // kv tiles: cap = CACHE+m0+128

    const int tid = threadIdx.x, lane = tid & 31, w = tid >> 5;
    const int g = lane >> 2, tq = lane & 3;
    const int wq0 = w << 4;                 // warp's q-row base

    const char* qb = (const char*)qs  + ((size_t)(b * SEQ + m0) * DIM + h * HDIM) * 2;
    const char* kb = (const char*)krs + (size_t)bh * TKV * HDIM * 2;
    const char* vb = (const char*)vts + (size_t)bh * HDIM * TKV * 2;

#define FLOADQ() do {                                                          \
    _Pragma("unroll")                                                          \
    for (int _i = 0; _i < 8; _i++) {                                           \
        const int _c = tid + (_i << 8);                                        \
        const int _r = _c >> 4, _cc = (_c & 15) << 4;                          \
        cp16(sbu + (uint32_t)(_r * RB + _cc), qb + (size_t)_r * (DIM*2) + _cc);\
    } } while (0)

#define FLOADT(T, BUF) do {                                                    \
    const uint32_t _kd = sbu + (uint32_t)(TSZ + (BUF) * TSZ);                  \
    const uint32_t _vd = sbu + (uint32_t)(3 * TSZ + (BUF) * TSZ);              \
    _Pragma("unroll")                                                          \
    for (int _i = 0; _i < 8; _i++) {                                           \
        const int _c = tid + (_i << 8);                                        \
        const int _r = _c >> 4, _cc = (_c & 15) << 4;                          \
        cp16(_kd + (uint32_t)(_r * RB + _cc),                                  \
             kb + (size_t)((T) * 128 + _r) * 256 + _cc);                       \
        cp16(_vd + (uint32_t)(_r * RB + _cc),                                  \
             vb + (size_t)_r * (TKV*2) + (size_t)(T) * 256 + _cc);             \
    } } while (0)

    FLOADQ();
    FLOADT(0, 0);
    CP_COMMIT();

    float accO[16][4];
#pragma unroll
    for (int i = 0; i < 16; i++)
#pragma unroll
        for (int j = 0; j < 4; j++) accO[i][j] = 0.f;
    float mr0 = -1.0e30f, mr1 = -1.0e30f, lr0 = 0.f, lr1 = 0.f;
    const float K2 = 0.08838834764831845f * 1.4426950408889634f; // scale*log2(e)

    for (int t = 0; t < nt; ++t) {
        if (t + 1 < nt) { FLOADT(t + 1, (t + 1) & 1); }
        CP_COMMIT();
        CP_WAIT1();
        __syncthreads();

        const char* K_ = Ks + (t & 1) * TSZ;
        const char* V_ = Vs + (t & 1) * TSZ;

        // ---- S = Q K^T  (16 x 128 per warp) --------------------------------
        float accS[16][4];
#pragma unroll
        for (int i = 0; i < 16; i++)
#pragma unroll
            for (int j = 0; j < 4; j++) accS[i][j] = 0.f;

#pragma unroll
        for (int kb8 = 0; kb8 < 8; kb8++) {
            const char* ap = Qs + (wq0 + g) * RB + (kb8 << 5) + (tq << 2);
            uint32_t a[4];
            a[0] = *(const uint32_t*)(ap);
            a[1] = *(const uint32_t*)(ap + 8 * RB);
            a[2] = *(const uint32_t*)(ap + 16);
            a[3] = *(const uint32_t*)(ap + 16 + 8 * RB);
#pragma unroll
            for (int nn = 0; nn < 16; nn++) {
                const char* bp = K_ + ((nn << 3) + g) * RB + (kb8 << 5) + (tq << 2);
                uint32_t b2[2];
                b2[0] = *(const uint32_t*)(bp);
                b2[1] = *(const uint32_t*)(bp + 16);
                mma_fp16(accS[nn], a, b2);
            }
        }

        // ---- causal mask (diagonal tile only) -------------------------------
        if (t == nt - 1) {
            const int r0 = wq0 + g, r1 = r0 + 8;
#pragma unroll
            for (int nn = 0; nn < 16; nn++) {
                const int c = (nn << 3) + (tq << 1);
                if (c     > r0) accS[nn][0] = -1.0e30f;
                if (c + 1 > r0) accS[nn][1] = -1.0e30f;
                if (c     > r1) accS[nn][2] = -1.0e30f;
                if (c + 1 > r1) accS[nn][3] = -1.0e30f;
            }
        }

        // ---- online softmax --------------------------------------------------
        float mx0 = -1.0e30f, mx1 = -1.0e30f;
#pragma unroll
        for (int nn = 0; nn < 16; nn++) {
            mx0 = fmaxf(mx0, fmaxf(accS[nn][0], accS[nn][1]));
            mx1 = fmaxf(mx1, fmaxf(accS[nn][2], accS[nn][3]));
        }
        mx0 = fmaxf(mx0, __shfl_xor_sync(0xffffffffu, mx0, 1));
        mx0 = fmaxf(mx0, __shfl_xor_sync(0xffffffffu, mx0, 2));
        mx1 = fmaxf(mx1, __shfl_xor_sync(0xffffffffu, mx1, 1));
        mx1 = fmaxf(mx1, __shfl_xor_sync(0xffffffffu, mx1, 2));
        const float mn0 = fmaxf(mr0, mx0), mn1 = fmaxf(mr1, mx1);
        const float al0 = exp2f(K2 * (mr0 - mn0));
        const float al1 = exp2f(K2 * (mr1 - mn1));
        mr0 = mn0; mr1 = mn1;

        float s0 = 0.f, s1 = 0.f;
        uint32_t P[16][2];
#pragma unroll
        for (int nn = 0; nn < 16; nn++) {
            const float p00 = exp2f(K2 * (accS[nn][0] - mn0));
            const float p01 = exp2f(K2 * (accS[nn][1] - mn0));
            const float p10 = exp2f(K2 * (accS[nn][2] - mn1));
            const float p11 = exp2f(K2 * (accS[nn][3] - mn1));
            s0 += p00 + p01; s1 += p10 + p11;
            P[nn][0] = pack_h2(p00, p01);
            P[nn][1] = pack_h2(p10, p11);
        }
        s0 += __shfl_xor_sync(0xffffffffu, s0, 1);
        s0 += __shfl_xor_sync(0xffffffffu, s0, 2);
        s1 += __shfl_xor_sync(0xffffffffu, s1, 1);
        s1 += __shfl_xor_sync(0xffffffffu, s1, 2);
        lr0 = lr0 * al0 + s0;
        lr1 = lr1 * al1 + s1;

#pragma unroll
        for (int dn = 0; dn < 16; dn++) {
            accO[dn][0] *= al0; accO[dn][1] *= al0;
            accO[dn][2] *= al1; accO[dn][3] *= al1;
        }

        // ---- O += P V  (P regs are the A fragments) --------------------------
#pragma unroll
        for (int kb8 = 0; kb8 < 8; kb8++) {
            uint32_t a[4];
            a[0] = P[2 * kb8][0];
            a[1] = P[2 * kb8][1];
            a[2] = P[2 * kb8 + 1][0];
            a[3] = P[2 * kb8 + 1][1];
#pragma unroll
            for (int dn = 0; dn < 16; dn++) {
                const char* bp = V_ + ((dn << 3) + g) * RB + (kb8 << 5) + (tq << 2);
                uint32_t b2[2];
                b2[0] = *(const uint32_t*)(bp);
                b2[1] = *(const uint32_t*)(bp + 16);
                mma_fp16(accO[dn], a, b2);
            }
        }
        __syncthreads();   // protect buffers before next prefetch overwrite
    }

    // ---- normalize + store ctx fp16 -----------------------------------------
    const float inv0 = 1.f / lr0, inv1 = 1.f / lr1;
    __half* c0 = cs + (size_t)(b * SEQ + m0 + wq0 + g) * DIM + h * HDIM;
    __half* c1 = c0 + (size_t)8 * DIM;
#pragma unroll
    for (int dn = 0; dn < 16; dn++) {
        const int c = (dn << 3) + (tq << 1);
        *(uint32_t*)(c0 + c) = pack_h2(accO[dn][0] * inv0, accO[dn][1] * inv0);
        *(uint32_t*)(c1 + c) = pack_h2(accO[dn][2] * inv1, accO[dn][3] * inv1);
    }
#undef FLOADQ
#undef FLOADT
}

// ---------------- fp32 -> fp16 conversion --------------------------------------
__global__ void to_half(const float4* __restrict__ src, __half* __restrict__ dst)
{
    const size_t i = (size_t)blockIdx.x * 256 + threadIdx.x;
    const float4 v = src[i];
    uint2 o;
    o.x = pack_h2(v.x, v.y);
    o.y = pack_h2(v.z, v.w);
    *(uint2*)(dst + i * 4) = o;
}

// ---------------- RoPE: q -> qs fp16; k -> xk fp32 + krs fp16; v -> xv --------
__global__ void rope_scatter(const float* __restrict__ q, const float* __restrict__ k,
                             const float* __restrict__ v,
                             const float* __restrict__ rope,
                             float* __restrict__ xk, float* __restrict__ xv,
                             __half* __restrict__ qs, __half* __restrict__ krs)
{
    const size_t idx = (size_t)blockIdx.x * 256 + threadIdx.x; // < 4194304
    const int j = (int)(idx & 63);
    const int h = (int)((idx >> 6) & 31);
    const int s = (int)((idx >> 11) & 1023);
    const int b = (int)(idx >> 21);

    const size_t src = ((size_t)(b * SEQ + s)) * DIM + h * HDIM + 2 * j;
    const float c  = rope[(size_t)(s * 64 + j) * 2];
    const float sn = rope[(size_t)(s * 64 + j) * 2 + 1];

    const float q0 = q[src], q1 = q[src + 1];
    *(uint32_t*)(qs + src) = pack_h2(q0 * c - q1 * sn, q0 * sn + q1 * c);

    const float k0 = k[src], k1 = k[src + 1];
    const float kr0 = k0 * c - k1 * sn;
    const float kr1 = k0 * sn + k1 * c;
    const size_t dst = (((size_t)(b * NHEADS + h)) * TKV + CACHE + s) * HDIM + 2 * j;
    xk[dst]     = kr0;
    xk[dst + 1] = kr1;
    *(uint32_t*)(krs + dst) = pack_h2(kr0, kr1);

    xv[dst]     = v[src];
    xv[dst + 1] = v[src + 1];
}

// ---------------- caches -> xk/xv fp32 + krs fp16 -------------------------------
__global__ void cache_copy(const float* __restrict__ kc,
                           const float* __restrict__ vc,
                           float* __restrict__ xk, float* __restrict__ xv,
                           __half* __restrict__ krs)
{
    const size_t i4  = (size_t)blockIdx.x * 256 + threadIdx.x; // < 2097152
    const size_t src = i4 * 4;
    const size_t bh  = src >> 17;              // / (CACHE*HDIM)
    const size_t dst = src + bh * (size_t)(CACHE * HDIM);
    const float4 kv = *(const float4*)(kc + src);
    *(float4*)(xk + dst) = kv;
    uint2 o;
    o.x = pack_h2(kv.x, kv.y);
    o.y = pack_h2(kv.z, kv.w);
    *(uint2*)(krs + dst) = o;
    *(float4*)(xv + dst) = *(const float4*)(vc + src);
}

// ---------------- transpose xv -> vts[b,h,d,t] fp16 -----------------------------
__global__ void transpose_v(const float* __restrict__ xv, __half* __restrict__ vts)
{
    __shared__ float tile[32][33];
    const int bh = blockIdx.z;
    const int t0 = blockIdx.x << 5, d0 = blockIdx.y << 5;
    const float* src = xv + (size_t)bh * TKV * HDIM;
    const int tx = threadIdx.x, ty = threadIdx.y;  // 32 x 8
#pragma unroll
    for (int i = 0; i < 32; i += 8)
        tile[ty + i][tx] = src[(size_t)(t0 + ty + i) * HDIM + d0 + tx];
    __syncthreads();
    const int tp = (tx & 15) << 1;        // t-pair: 0,2,..,30
    const int rr = ((tx >> 4) << 3) + ty; // 0..15
#pragma unroll
    for (int i = 0; i < 32; i += 16) {
        const int d = rr + i;
        const size_t ev = ((size_t)bh * HDIM + d0 + d) * TKV + t0 + tp;
        *(uint32_t*)(vts + ev) = pack_h2(tile[tp][d], tile[tp + 1][d]);
    }
}

// ---------------- launch --------------------------------------------------------
extern "C" void kernel_launch(void* const* d_in, const int* in_sizes, int n_in,
                              void* d_out, int out_size)
{
    const float* x    = (const float*)d_in[0];
    const float* kc   = (const float*)d_in[1];
    const float* vc   = (const float*)d_in[2];
    const float* rope = (const float*)d_in[3];
    const float* Wq   = (const float*)d_in[4];
    const float* Wk   = (const float*)d_in[5];
    const float* Wv   = (const float*)d_in[6];
    const float* Wo   = (const float*)d_in[7];

    float* out = (float*)d_out;
    float* xk  = out + (size_t)BSZ * SEQ * DIM;               // +8388608
    float* xv  = xk + (size_t)BSZ * NHEADS * TKV * HDIM;      // +16777216

    __half *xs, *wqs, *wks, *wvs, *wos, *qs, *krs, *vts, *cs;
    float *q, *k, *v;
    cudaGetSymbolAddress((void**)&xs,  g_xs);
    cudaGetSymbolAddress((void**)&wqs, g_wqs);
    cudaGetSymbolAddress((void**)&wks, g_wks);
    cudaGetSymbolAddress((void**)&wvs, g_wvs);
    cudaGetSymbolAddress((void**)&wos, g_wos);
    cudaGetSymbolAddress((void**)&q,   g_q);
    cudaGetSymbolAddress((void**)&k,   g_k);
    cudaGetSymbolAddress((void**)&v,   g_v);
    cudaGetSymbolAddress((void**)&qs,  g_qs);
    cudaGetSymbolAddress((void**)&krs, g_krs);
    cudaGetSymbolAddress((void**)&vts, g_vts);
    cudaGetSymbolAddress((void**)&cs,  g_cs);

    const int GSMEM = 3 * 256 * 144;        // 110592 bytes -> 2 CTA/SM
    const int FSMEM = 5 * 128 * 272;        // Q + 2K + 2V = 174080 bytes
    static int smem_set = 0;
    if (!smem_set) {
        cudaFuncSetAttribute(gemm_fp16,  cudaFuncAttributeMaxDynamicSharedMemorySize, GSMEM);
        cudaFuncSetAttribute(flash_attn, cudaFuncAttributeMaxDynamicSharedMemorySize, FSMEM);
        smem_set = 1;
    }

    const dim3 blk(256);

    // convert inputs to fp16
    to_half<<<MROWS * DIM / 1024, blk>>>((const float4*)x,  xs);
    to_half<<<DIM * DIM / 1024,   blk>>>((const float4*)Wq, wqs);
    to_half<<<DIM * DIM / 1024,   blk>>>((const float4*)Wk, wks);
    to_half<<<DIM * DIM / 1024,   blk>>>((const float4*)Wv, wvs);

    // Q/K/V projections (fp32 outputs)
    const dim3 gp(DIM / 128, MROWS / 128, 1);
    gemm_fp16<<<gp, blk, GSMEM>>>((const char*)xs, (const char*)wqs, (char*)q,
                                  DIM, DIM*2, DIM*2, DIM*4, 0);
    gemm_fp16<<<gp, blk, GSMEM>>>((const char*)xs, (const char*)wks, (char*)k,
                                  DIM, DIM*2, DIM*2, DIM*4, 0);
    gemm_fp16<<<gp, blk, GSMEM>>>((const char*)xs, (const char*)wvs, (char*)v,
                                  DIM, DIM*2, DIM*2, DIM*4, 0);

    to_half<<<DIM * DIM / 1024,   blk>>>((const float4*)Wo, wos);

    cache_copy<<<8192, blk>>>(kc, vc, xk, xv, krs);
    rope_scatter<<<16384, blk>>>(q, k, v, rope, xk, xv, qs, krs);
    transpose_v<<<dim3(TKV / 32, HDIM / 32, BSZ * NHEADS), dim3(32, 8)>>>(xv, vts);

    // fused attention: scores + causal softmax + PV -> ctx fp16
    flash_attn<<<dim3(SEQ / 128, BSZ * NHEADS), blk, FSMEM>>>(qs, krs, vts, cs);

    // output = ctx @ Wo^T  (fp32 out)
    gemm_fp16<<<gp, blk, GSMEM>>>((const char*)cs, (const char*)wos, (char*)out,
                                  DIM, DIM*2, DIM*2, DIM*4, 0);
}

// round 9
// speedup vs baseline: 2.6693x; 1.1083x over previous
#include <cuda_runtime.h>
#include <cuda_fp16.h>
#include <cstdint>
#include <cstddef>

#define DIM     4096
#define HDIM    128
#define NHEADS  32
#define BSZ     2
#define SEQ     1024
#define CACHE   1024
#define TKV     2048
#define MROWS   2048   // BSZ*SEQ

// ---------------- scratch (static device memory; no allocations allowed) ----
static __device__ __align__(16) __half g_xs  [(size_t)MROWS * DIM];
static __device__ __align__(16) __half g_wqkv[(size_t)3 * DIM * DIM];   // [Wq;Wk;Wv] fp16
static __device__ __align__(16) __half g_wos [(size_t)DIM * DIM];
static __device__ __align__(16) __half g_qs  [(size_t)MROWS * DIM];               // roped q
static __device__ __align__(16) __half g_krs [(size_t)BSZ * NHEADS * TKV * HDIM]; // roped k + cache
static __device__ __align__(16) __half g_vts [(size_t)BSZ * NHEADS * HDIM * TKV]; // v^T
static __device__ __align__(16) __half g_cs  [(size_t)MROWS * DIM];               // ctx

// ---------------- helpers -----------------------------------------------------
__device__ __forceinline__ uint32_t smem_u32(const void* p) {
    uint32_t a;
    asm("{ .reg .u64 t; cvta.to.shared.u64 t, %1; cvt.u32.u64 %0, t; }"
        : "=r"(a) : "l"(p));
    return a;
}

__device__ __forceinline__ void cp16(uint32_t dst, const void* src) {
    asm volatile("cp.async.cg.shared.global [%0], [%1], 16;"
                 :: "r"(dst), "l"(src));
}
#define CP_COMMIT() asm volatile("cp.async.commit_group;" ::: "memory")
#define CP_WAIT1()  asm volatile("cp.async.wait_group 1;"  ::: "memory")

__device__ __forceinline__ void mma_fp16(float c[4], const uint32_t a[4],
                                         const uint32_t b[2]) {
    asm volatile(
        "mma.sync.aligned.m16n8k16.row.col.f32.f16.f16.f32 "
        "{%0,%1,%2,%3},{%4,%5,%6,%7},{%8,%9},{%0,%1,%2,%3};\n"
        : "+f"(c[0]), "+f"(c[1]), "+f"(c[2]), "+f"(c[3])
        : "r"(a[0]), "r"(a[1]), "r"(a[2]), "r"(a[3]),
          "r"(b[0]), "r"(b[1]));
}

__device__ __forceinline__ uint32_t pack_h2(float x, float y) {
    __half2 h = __floats2half2_rn(x, y);     // x -> low half (element order)
    return *(uint32_t*)&h;
}

// ---------------- fp16 pipelined NT GEMM ----------------------------------------
// C[M,N] = A[M,K] * B[N,K]^T, fp16 in, fp32 accumulate.
// Block 128x128, K-chunk 64, 3-stage cp.async, 256 thr (8 warps 2Mx4N).
// mode 0: plain fp32 C store (ldcB byte stride).
// mode 1: fused QKV epilogue. Weight section = n0>>12 (0:Q 1:K 2:V).
//   Q: rope-rotate, fp16 -> qs.   K: rope-rotate, fp32 -> xk AND fp16 -> krs
//   at cache-scattered offset.    V: fp32 -> xv at cache-scattered offset.
__global__ __launch_bounds__(256, 2) void gemm_fp16(
    const char* __restrict__ Ag, const char* __restrict__ Bg,
    char* __restrict__ Cg, int K, int ldaB, int ldbB, int ldcB, int mode,
    __half* __restrict__ qsO, float* __restrict__ xkO,
    __half* __restrict__ krsO, float* __restrict__ xvO,
    const float* __restrict__ rope)
{
    constexpr int ROWB = 144;
    constexpr int BOFF = 128 * ROWB;
    constexpr int SWB  = 256 * ROWB;
    extern __shared__ char smem[];

    const int m0 = blockIdx.y << 7;
    const int n0 = blockIdx.x << 7;
    const int nt = K >> 6;

    const int tid  = threadIdx.x;
    const int lane = tid & 31, w = tid >> 5;
    const int wm = (w & 1) << 6;
    const int wn = (w >> 1) << 5;
    const int g  = lane >> 2, tq = lane & 3;

    const int crow = tid >> 3;
    const int off  = (tid & 7) << 4;
    const char* aP = Ag + (size_t)(m0 + crow) * ldaB + off;
    const char* bP = Bg + (size_t)(n0 + crow) * ldbB + off;
    const uint32_t sbu = smem_u32(smem);
    const uint32_t dA = sbu + (uint32_t)(crow * ROWB + off);
    const uint32_t dB = dA + BOFF;

    float acc[4][4][4];
#pragma unroll
    for (int i = 0; i < 4; i++)
#pragma unroll
        for (int j = 0; j < 4; j++)
#pragma unroll
            for (int l = 0; l < 4; l++) acc[i][j][l] = 0.f;

#define ISSUE(SOFF, T) do {                                                    \
    _Pragma("unroll")                                                          \
    for (int _i = 0; _i < 4; _i++)                                             \
        cp16(dA + (SOFF) + (uint32_t)(_i * 32 * ROWB),                         \
             aP + (size_t)(T) * 128 + (size_t)(_i * 32) * ldaB);               \
    _Pragma("unroll")                                                          \
    for (int _i = 0; _i < 4; _i++)                                             \
        cp16(dB + (SOFF) + (uint32_t)(_i * 32 * ROWB),                         \
             bP + (size_t)(T) * 128 + (size_t)(_i * 32) * ldbB);               \
} while (0)

#define COMPUTE(BUF) do {                                                      \
    const char* Ab = smem + (BUF) * SWB;                                       \
    const char* Bb = Ab + BOFF;                                                \
    _Pragma("unroll")                                                          \
    for (int s16 = 0; s16 < 4; s16++) {                                        \
        const int kb = s16 << 5;                                               \
        uint32_t bf[4][2];                                                     \
        _Pragma("unroll")                                                      \
        for (int nn = 0; nn < 4; nn++) {                                       \
            const char* bp = Bb + (wn + (nn << 3) + g) * ROWB + kb + (tq << 2);\
            bf[nn][0] = *(const uint32_t*)(bp);                                \
            bf[nn][1] = *(const uint32_t*)(bp + 16);                           \
        }                                                                      \
        _Pragma("unroll")                                                      \
        for (int mt = 0; mt < 4; mt++) {                                       \
            const char* ap = Ab + (wm + (mt << 4) + g) * ROWB + kb + (tq << 2);\
            uint32_t af[4];                                                    \
            af[0] = *(const uint32_t*)(ap);                                    \
            af[1] = *(const uint32_t*)(ap + 8 * ROWB);                         \
            af[2] = *(const uint32_t*)(ap + 16);                               \
            af[3] = *(const uint32_t*)(ap + 16 + 8 * ROWB);                    \
            _Pragma("unroll")                                                  \
            for (int nn = 0; nn < 4; nn++)                                     \
                mma_fp16(acc[mt][nn], af, bf[nn]);                             \
        }                                                                      \
    }                                                                          \
} while (0)

    ISSUE(0u, 0);            CP_COMMIT();
    ISSUE((uint32_t)SWB, 1); CP_COMMIT();

    int buf = 0;
    for (int t = 0; t < nt; ++t) {
        CP_WAIT1();
        __syncthreads();
        if (t + 2 < nt) {
            int nb = buf + 2; if (nb >= 3) nb -= 3;
            ISSUE((uint32_t)(nb * SWB), t + 2);
        }
        CP_COMMIT();
        COMPUTE(buf);
        buf = (buf == 2) ? 0 : buf + 1;
    }

    if (mode == 0) {
#pragma unroll
        for (int mt = 0; mt < 4; mt++) {
#pragma unroll
            for (int nn = 0; nn < 4; nn++) {
                const int row = m0 + wm + (mt << 4) + g;
                const int col = n0 + wn + (nn << 3) + (tq << 1);
                float2 v0; v0.x = acc[mt][nn][0]; v0.y = acc[mt][nn][1];
                float2 v1; v1.x = acc[mt][nn][2]; v1.y = acc[mt][nn][3];
                *(float2*)((float*)(Cg + (size_t)row * ldcB) + col)       = v0;
                *(float2*)((float*)(Cg + (size_t)(row + 8) * ldcB) + col) = v1;
            }
        }
    } else {
        const int sect = n0 >> 12;           // 0:Q 1:K 2:V (CTA-uniform)
#pragma unroll
        for (int mt = 0; mt < 4; mt++) {
#pragma unroll
            for (int nn = 0; nn < 4; nn++) {
                const int col = n0 + wn + (nn << 3) + (tq << 1);
                const int f = col & 4095;            // feature index
                const int h = f >> 7, d = f & 127, j = d >> 1;
#pragma unroll
                for (int half8 = 0; half8 < 2; half8++) {
                    const int row = m0 + wm + (mt << 4) + g + (half8 << 3);
                    const float a0 = acc[mt][nn][half8 << 1];
                    const float a1 = acc[mt][nn][(half8 << 1) + 1];
                    const int b = row >> 10, s = row & 1023;
                    if (sect == 2) {
                        const size_t dst =
                            (((size_t)(b * NHEADS + h)) * TKV + CACHE + s) * HDIM + d;
                        float2 vv; vv.x = a0; vv.y = a1;
                        *(float2*)(xvO + dst) = vv;
                    } else {
                        const float2 cs2 = *(const float2*)(rope + (size_t)(s * 64 + j) * 2);
                        const float r0 = a0 * cs2.x - a1 * cs2.y;
                        const float r1 = a0 * cs2.y + a1 * cs2.x;
                        if (sect == 0) {
                            *(uint32_t*)(qsO + (size_t)row * DIM + f) = pack_h2(r0, r1);
                        } else {
                            const size_t dst =
                                (((size_t)(b * NHEADS + h)) * TKV + CACHE + s) * HDIM + d;
                            float2 vv; vv.x = r0; vv.y = r1;
                            *(float2*)(xkO + dst) = vv;
                            *(uint32_t*)(krsO + dst) = pack_h2(r0, r1);
                        }
                    }
                }
            }
        }
    }
#undef ISSUE
#undef COMPUTE
}

// ---------------- fused flash attention -----------------------------------------
__global__ __launch_bounds__(256) void flash_attn(
    const __half* __restrict__ qs, const __half* __restrict__ krs,
    const __half* __restrict__ vts, __half* __restrict__ cs)
{
    constexpr int RB  = 272;
    constexpr int TSZ = 128 * RB;
    extern __shared__ char smem[];
    char* Qs = smem;
    char* Ks = smem + TSZ;
    char* Vs = smem + 3 * TSZ;
    const uint32_t sbu = smem_u32(smem);

    const int qblk = 7 - blockIdx.x;
    const int bh   = blockIdx.y;
    const int b    = bh >> 5;
    const int h    = bh & 31;
    const int m0   = qblk << 7;
    const int nt   = 9 + qblk;

    const int tid = threadIdx.x, lane = tid & 31, w = tid >> 5;
    const int g = lane >> 2, tq = lane & 3;
    const int wq0 = w << 4;

    const char* qb = (const char*)qs  + ((size_t)(b * SEQ + m0) * DIM + h * HDIM) * 2;
    const char* kb = (const char*)krs + (size_t)bh * TKV * HDIM * 2;
    const char* vb = (const char*)vts + (size_t)bh * HDIM * TKV * 2;

#define FLOADQ() do {                                                          \
    _Pragma("unroll")                                                          \
    for (int _i = 0; _i < 8; _i++) {                                           \
        const int _c = tid + (_i << 8);                                        \
        const int _r = _c >> 4, _cc = (_c & 15) << 4;                          \
        cp16(sbu + (uint32_t)(_r * RB + _cc), qb + (size_t)_r * (DIM*2) + _cc);\
    } } while (0)

#define FLOADT(T, BUF) do {                                                    \
    const uint32_t _kd = sbu + (uint32_t)(TSZ + (BUF) * TSZ);                  \
    const uint32_t _vd = sbu + (uint32_t)(3 * TSZ + (BUF) * TSZ);              \
    _Pragma("unroll")                                                          \
    for (int _i = 0; _i < 8; _i++) {                                           \
        const int _c = tid + (_i << 8);                                        \
        const int _r = _c >> 4, _cc = (_c & 15) << 4;                          \
        cp16(_kd + (uint32_t)(_r * RB + _cc),                                  \
             kb + (size_t)((T) * 128 + _r) * 256 + _cc);                       \
        cp16(_vd + (uint32_t)(_r * RB + _cc),                                  \
             vb + (size_t)_r * (TKV*2) + (size_t)(T) * 256 + _cc);             \
    } } while (0)

    FLOADQ();
    FLOADT(0, 0);
    CP_COMMIT();

    float accO[16][4];
#pragma unroll
    for (int i = 0; i < 16; i++)
#pragma unroll
        for (int j = 0; j < 4; j++) accO[i][j] = 0.f;
    float mr0 = -1.0e30f, mr1 = -1.0e30f, lr0 = 0.f, lr1 = 0.f;
    const float K2 = 0.08838834764831845f * 1.4426950408889634f;

    for (int t = 0; t < nt; ++t) {
        if (t + 1 < nt) { FLOADT(t + 1, (t + 1) & 1); }
        CP_COMMIT();
        CP_WAIT1();
        __syncthreads();

        const char* K_ = Ks + (t & 1) * TSZ;
        const char* V_ = Vs + (t & 1) * TSZ;

        float accS[16][4];
#pragma unroll
        for (int i = 0; i < 16; i++)
#pragma unroll
            for (int j = 0; j < 4; j++) accS[i][j] = 0.f;

#pragma unroll
        for (int kb8 = 0; kb8 < 8; kb8++) {
            const char* ap = Qs + (wq0 + g) * RB + (kb8 << 5) + (tq << 2);
            uint32_t a[4];
            a[0] = *(const uint32_t*)(ap);
            a[1] = *(const uint32_t*)(ap + 8 * RB);
            a[2] = *(const uint32_t*)(ap + 16);
            a[3] = *(const uint32_t*)(ap + 16 + 8 * RB);
#pragma unroll
            for (int nn = 0; nn < 16; nn++) {
                const char* bp = K_ + ((nn << 3) + g) * RB + (kb8 << 5) + (tq << 2);
                uint32_t b2[2];
                b2[0] = *(const uint32_t*)(bp);
                b2[1] = *(const uint32_t*)(bp + 16);
                mma_fp16(accS[nn], a, b2);
            }
        }

        if (t == nt - 1) {
            const int r0 = wq0 + g, r1 = r0 + 8;
#pragma unroll
            for (int nn = 0; nn < 16; nn++) {
                const int c = (nn << 3) + (tq << 1);
                if (c     > r0) accS[nn][0] = -1.0e30f;
                if (c + 1 > r0) accS[nn][1] = -1.0e30f;
                if (c     > r1) accS[nn][2] = -1.0e30f;
                if (c + 1 > r1) accS[nn][3] = -1.0e30f;
            }
        }

        float mx0 = -1.0e30f, mx1 = -1.0e30f;
#pragma unroll
        for (int nn = 0; nn < 16; nn++) {
            mx0 = fmaxf(mx0, fmaxf(accS[nn][0], accS[nn][1]));
            mx1 = fmaxf(mx1, fmaxf(accS[nn][2], accS[nn][3]));
        }
        mx0 = fmaxf(mx0, __shfl_xor_sync(0xffffffffu, mx0, 1));
        mx0 = fmaxf(mx0, __shfl_xor_sync(0xffffffffu, mx0, 2));
        mx1 = fmaxf(mx1, __shfl_xor_sync(0xffffffffu, mx1, 1));
        mx1 = fmaxf(mx1, __shfl_xor_sync(0xffffffffu, mx1, 2));
        const float mn0 = fmaxf(mr0, mx0), mn1 = fmaxf(mr1, mx1);
        const float al0 = exp2f(K2 * (mr0 - mn0));
        const float al1 = exp2f(K2 * (mr1 - mn1));
        mr0 = mn0; mr1 = mn1;

        float s0 = 0.f, s1 = 0.f;
        uint32_t P[16][2];
#pragma unroll
        for (int nn = 0; nn < 16; nn++) {
            const float p00 = exp2f(K2 * (accS[nn][0] - mn0));
            const float p01 = exp2f(K2 * (accS[nn][1] - mn0));
            const float p10 = exp2f(K2 * (accS[nn][2] - mn1));
            const float p11 = exp2f(K2 * (accS[nn][3] - mn1));
            s0 += p00 + p01; s1 += p10 + p11;
            P[nn][0] = pack_h2(p00, p01);
            P[nn][1] = pack_h2(p10, p11);
        }
        s0 += __shfl_xor_sync(0xffffffffu, s0, 1);
        s0 += __shfl_xor_sync(0xffffffffu, s0, 2);
        s1 += __shfl_xor_sync(0xffffffffu, s1, 1);
        s1 += __shfl_xor_sync(0xffffffffu, s1, 2);
        lr0 = lr0 * al0 + s0;
        lr1 = lr1 * al1 + s1;

#pragma unroll
        for (int dn = 0; dn < 16; dn++) {
            accO[dn][0] *= al0; accO[dn][1] *= al0;
            accO[dn][2] *= al1; accO[dn][3] *= al1;
        }

#pragma unroll
        for (int kb8 = 0; kb8 < 8; kb8++) {
            uint32_t a[4];
            a[0] = P[2 * kb8][0];
            a[1] = P[2 * kb8][1];
            a[2] = P[2 * kb8 + 1][0];
            a[3] = P[2 * kb8 + 1][1];
#pragma unroll
            for (int dn = 0; dn < 16; dn++) {
                const char* bp = V_ + ((dn << 3) + g) * RB + (kb8 << 5) + (tq << 2);
                uint32_t b2[2];
                b2[0] = *(const uint32_t*)(bp);
                b2[1] = *(const uint32_t*)(bp + 16);
                mma_fp16(accO[dn], a, b2);
            }
        }
        __syncthreads();
    }

    const float inv0 = 1.f / lr0, inv1 = 1.f / lr1;
    __half* c0 = cs + (size_t)(b * SEQ + m0 + wq0 + g) * DIM + h * HDIM;
    __half* c1 = c0 + (size_t)8 * DIM;
#pragma unroll
    for (int dn = 0; dn < 16; dn++) {
        const int c = (dn << 3) + (tq << 1);
        *(uint32_t*)(c0 + c) = pack_h2(accO[dn][0] * inv0, accO[dn][1] * inv0);
        *(uint32_t*)(c1 + c) = pack_h2(accO[dn][2] * inv1, accO[dn][3] * inv1);
    }
#undef FLOADQ
#undef FLOADT
}

// ---------------- fp32 -> fp16 conversion --------------------------------------
__global__ void to_half(const float4* __restrict__ src, __half* __restrict__ dst)
{
    const size_t i = (size_t)blockIdx.x * 256 + threadIdx.x;
    const float4 v = src[i];
    uint2 o;
    o.x = pack_h2(v.x, v.y);
    o.y = pack_h2(v.z, v.w);
    *(uint2*)(dst + i * 4) = o;
}

// ---------------- caches -> xk/xv fp32 + krs fp16 -------------------------------
__global__ void cache_copy(const float* __restrict__ kc,
                           const float* __restrict__ vc,
                           float* __restrict__ xk, float* __restrict__ xv,
                           __half* __restrict__ krs)
{
    const size_t i4  = (size_t)blockIdx.x * 256 + threadIdx.x; // < 2097152
    const size_t src = i4 * 4;
    const size_t bh  = src >> 17;              // / (CACHE*HDIM)
    const size_t dst = src + bh * (size_t)(CACHE * HDIM);
    const float4 kv = *(const float4*)(kc + src);
    *(float4*)(xk + dst) = kv;
    uint2 o;
    o.x = pack_h2(kv.x, kv.y);
    o.y = pack_h2(kv.z, kv.w);
    *(uint2*)(krs + dst) = o;
    *(float4*)(xv + dst) = *(const float4*)(vc + src);
}

// ---------------- transpose xv -> vts[b,h,d,t] fp16 -----------------------------
__global__ void transpose_v(const float* __restrict__ xv, __half* __restrict__ vts)
{
    __shared__ float tile[32][33];
    const int bh = blockIdx.z;
    const int t0 = blockIdx.x << 5, d0 = blockIdx.y << 5;
    const float* src = xv + (size_t)bh * TKV * HDIM;
    const int tx = threadIdx.x, ty = threadIdx.y;  // 32 x 8
#pragma unroll
    for (int i = 0; i < 32; i += 8)
        tile[ty + i][tx] = src[(size_t)(t0 + ty + i) * HDIM + d0 + tx];
    __syncthreads();
    const int tp = (tx & 15) << 1;
    const int rr = ((tx >> 4) << 3) + ty;
#pragma unroll
    for (int i = 0; i < 32; i += 16) {
        const int d = rr + i;
        const size_t ev = ((size_t)bh * HDIM + d0 + d) * TKV + t0 + tp;
        *(uint32_t*)(vts + ev) = pack_h2(tile[tp][d], tile[tp + 1][d]);
    }
}

// ---------------- launch --------------------------------------------------------
extern "C" void kernel_launch(void* const* d_in, const int* in_sizes, int n_in,
                              void* d_out, int out_size)
{
    const float* x    = (const float*)d_in[0];
    const float* kc   = (const float*)d_in[1];
    const float* vc   = (const float*)d_in[2];
    const float* rope = (const float*)d_in[3];
    const float* Wq   = (const float*)d_in[4];
    const float* Wk   = (const float*)d_in[5];
    const float* Wv   = (const float*)d_in[6];
    const float* Wo   = (const float*)d_in[7];

    float* out = (float*)d_out;
    float* xk  = out + (size_t)BSZ * SEQ * DIM;               // +8388608
    float* xv  = xk + (size_t)BSZ * NHEADS * TKV * HDIM;      // +16777216

    __half *xs, *wqkv, *wos, *qs, *krs, *vts, *cs;
    cudaGetSymbolAddress((void**)&xs,   g_xs);
    cudaGetSymbolAddress((void**)&wqkv, g_wqkv);
    cudaGetSymbolAddress((void**)&wos,  g_wos);
    cudaGetSymbolAddress((void**)&qs,   g_qs);
    cudaGetSymbolAddress((void**)&krs,  g_krs);
    cudaGetSymbolAddress((void**)&vts,  g_vts);
    cudaGetSymbolAddress((void**)&cs,   g_cs);

    const int GSMEM = 3 * 256 * 144;        // 110592 bytes -> 2 CTA/SM
    const int FSMEM = 5 * 128 * 272;        // Q + 2K + 2V = 174080 bytes
    static int smem_set = 0;
    if (!smem_set) {
        cudaFuncSetAttribute(gemm_fp16,  cudaFuncAttributeMaxDynamicSharedMemorySize, GSMEM);
        cudaFuncSetAttribute(flash_attn, cudaFuncAttributeMaxDynamicSharedMemorySize, FSMEM);
        smem_set = 1;
    }

    const dim3 blk(256);

    // convert inputs to fp16 (weights into one contiguous [3*DIM, DIM] buffer)
    to_half<<<MROWS * DIM / 1024, blk>>>((const float4*)x,  xs);
    to_half<<<DIM * DIM / 1024,   blk>>>((const float4*)Wq, wqkv);
    to_half<<<DIM * DIM / 1024,   blk>>>((const float4*)Wk, wqkv + (size_t)DIM * DIM);
    to_half<<<DIM * DIM / 1024,   blk>>>((const float4*)Wv, wqkv + (size_t)2 * DIM * DIM);

    // cache halves of xk/xv/krs (independent of projections)
    cache_copy<<<8192, blk>>>(kc, vc, xk, xv, krs);

    // fused QKV projection + rope + scatter
    const dim3 gqkv(3 * DIM / 128, MROWS / 128, 1);
    gemm_fp16<<<gqkv, blk, GSMEM>>>((const char*)xs, (const char*)wqkv, nullptr,
                                    DIM, DIM*2, DIM*2, 0, 1,
                                    qs, xk, krs, xv, rope);

    to_half<<<DIM * DIM / 1024, blk>>>((const float4*)Wo, wos);

    transpose_v<<<dim3(TKV / 32, HDIM / 32, BSZ * NHEADS), dim3(32, 8)>>>(xv, vts);

    // fused attention: scores + causal softmax + PV -> ctx fp16
    flash_attn<<<dim3(SEQ / 128, BSZ * NHEADS), blk, FSMEM>>>(qs, krs, vts, cs);

    // output = ctx @ Wo^T  (fp32 out)
    const dim3 gp(DIM / 128, MROWS / 128, 1);
    gemm_fp16<<<gp, blk, GSMEM>>>((const char*)cs, (const char*)wos, (char*)out,
                                  DIM, DIM*2, DIM*2, DIM*4, 0,
                                  nullptr, nullptr, nullptr, nullptr, nullptr);
}